// round 3
// baseline (speedup 1.0000x reference)
#include <cuda_runtime.h>
#include <cstdint>

#define N_FINE   200000
#define N_COARSE 50000
#define ROW_F4   128   // (2 groups * 128 ch * 2 cplx) floats / 4 = 128 float4 per row

// ---------- device scratch (no runtime allocation allowed) ----------
struct __align__(16) EdgeRec { int src; int dst; float c; float s; };
__device__ EdgeRec g_edge[N_FINE];     // 3.2 MB: fully resolved per-edge record

// ---------- phase 1: resolve edges in ONE kernel ----------
// unpool_nodes is sorted and every edge_src value is guaranteed to be a member
// (reference draws edge_src FROM unpool_nodes), so a lower_bound binary search
// recovers the coarse index exactly — no inverse-permutation table needed.
__global__ void build_edge_kernel(const int*    __restrict__ nodes,
                                  const int*    __restrict__ edge_src,
                                  const int*    __restrict__ edge_dst,
                                  const float2* __restrict__ conn) {
    int e = blockIdx.x * blockDim.x + threadIdx.x;
    if (e >= N_FINE) return;

    int target = edge_src[e];
    int lo = 0, hi = N_COARSE - 1;
    #pragma unroll 4
    while (lo < hi) {                      // 16 iterations; nodes[] lives in L1/L2
        int mid = (lo + hi) >> 1;
        if (__ldg(&nodes[mid]) < target) lo = mid + 1; else hi = mid;
    }

    EdgeRec r;
    r.src = lo;
    r.dst = edge_dst[e];
    float2 cs = conn[e];
    r.c = cs.x;
    r.s = cs.y;
    g_edge[e] = r;
}

// ---------- phase 2: gather row, rotate group 1, scatter ----------
// One warp per edge (32 threads). Thread j handles float4s j, j+32 (group 0:
// plain copy) and j+64, j+96 (group 1: multiply by conj(c,s)). All 4 loads
// issue back-to-back -> MLP=4 per thread. Metadata load is warp-uniform.
// Streaming stores keep the touch-once 410 MB output from evicting the
// 102 MB reused x working set out of L2.
__global__ void __launch_bounds__(256)
unpool_kernel(const float4* __restrict__ x, float4* __restrict__ out) {
    int t = blockIdx.x * blockDim.x + threadIdx.x;
    int e = t >> 5;        // edge index — uniform across the warp
    int j = t & 31;        // float4 lane
    if (e >= N_FINE) return;

    // Single warp-uniform 16-byte load for all per-edge metadata.
    int4 raw = *reinterpret_cast<const int4*>(&g_edge[e]);
    int   src = raw.x;
    int   dst = raw.y;
    float c   = __int_as_float(raw.z);
    float s   = __int_as_float(raw.w);

    const float4* xr = x + (size_t)src * ROW_F4;
    float4 v0 = xr[j];          // group 0
    float4 v1 = xr[j + 32];     // group 0
    float4 v2 = xr[j + 64];     // group 1
    float4 v3 = xr[j + 96];     // group 1

    // (re + i*im) * (c - i*s)
    float4 r2, r3;
    r2.x = fmaf(v2.x, c,  v2.y * s);
    r2.y = fmaf(v2.y, c, -v2.x * s);
    r2.z = fmaf(v2.z, c,  v2.w * s);
    r2.w = fmaf(v2.w, c, -v2.z * s);
    r3.x = fmaf(v3.x, c,  v3.y * s);
    r3.y = fmaf(v3.y, c, -v3.x * s);
    r3.z = fmaf(v3.z, c,  v3.w * s);
    r3.w = fmaf(v3.w, c, -v3.z * s);

    float4* o = out + (size_t)dst * ROW_F4;
    __stcs(o + j,      v0);
    __stcs(o + j + 32, v1);
    __stcs(o + j + 64, r2);
    __stcs(o + j + 96, r3);
}

extern "C" void kernel_launch(void* const* d_in, const int* in_sizes, int n_in,
                              void* d_out, int out_size) {
    // metadata order: x, unpool_connection, unpool_nodes, unpool_edges, num_nodes
    const float4* x     = (const float4*)d_in[0];
    const float2* conn  = (const float2*)d_in[1];
    const int*    nodes = (const int*)d_in[2];
    const int*    edges = (const int*)d_in[3];   // [2, N_FINE]: row0=src, row1=dst
    float4*       out   = (float4*)d_out;

    (void)in_sizes; (void)n_in; (void)out_size;

    build_edge_kernel<<<(N_FINE + 255) / 256, 256>>>(nodes, edges, edges + N_FINE, conn);

    const long long total = (long long)N_FINE * 32;   // 6.4M threads
    unpool_kernel<<<(unsigned)((total + 255) / 256), 256>>>(x, out);
}